// round 4
// baseline (speedup 1.0000x reference)
#include <cuda_runtime.h>
#include <cstddef>

// Problem dims (fixed by the dataset)
#define INSIZE  2048
#define HSIZE   4096
#define OUTSIZE 2048

// ---------------- device scratch (no allocations allowed) ----------------
__device__ float g_h1[HSIZE];
__device__ float g_m1[HSIZE];
__device__ float g_h2[HSIZE];
__device__ float g_m2[HSIZE];
__device__ float g_Et[(size_t)HSIZE * OUTSIZE];            // compacted Et (tf32 bits)
__device__ float g_A1[(size_t)HSIZE * HSIZE];              // W2^T[idx1][idx2] (tf32 bits)
__device__ float g_A2[(size_t)INSIZE * HSIZE];             // W1^T[:, idx1] (tf32 bits)
__device__ float g_B1[(size_t)HSIZE * OUTSIZE];            // W3^T rows idx2 (tf32 bits)
__device__ int   g_idx1[HSIZE];
__device__ int   g_idx2[HSIZE];
__device__ int   g_cnt1[2];   // [raw, padded-to-32]
__device__ int   g_cnt2[2];
__device__ int   g_c2048[2] = {INSIZE, INSIZE};

__device__ __forceinline__ unsigned f2tf32(float f) {
    unsigned r;
    asm volatile("cvt.rna.tf32.f32 %0, %1;" : "=r"(r) : "f"(f));
    return r;
}
__device__ __forceinline__ float f2tf32f(float f) { return __uint_as_float(f2tf32(f)); }

// ---------------- fp32 GEMV: z = W @ v, optional ReLU mask ----------------
__global__ void gemv_kernel(const float* __restrict__ W, const float* __restrict__ v,
                            float* __restrict__ h, float* __restrict__ mask, int K)
{
    int row = blockIdx.x;
    const float* w = W + (size_t)row * K;
    float acc = 0.f;
    for (int i = threadIdx.x * 4; i < K; i += blockDim.x * 4) {
        float4 a = *(const float4*)(w + i);
        float4 b = *(const float4*)(v + i);
        acc += a.x * b.x + a.y * b.y + a.z * b.z + a.w * b.w;
    }
    __shared__ float red[256];
    red[threadIdx.x] = acc;
    __syncthreads();
    for (int s = 128; s > 0; s >>= 1) {
        if (threadIdx.x < s) red[threadIdx.x] += red[threadIdx.x + s];
        __syncthreads();
    }
    if (threadIdx.x == 0) {
        float z = red[0];
        if (mask) {
            float m = z > 0.f ? 1.f : 0.f;
            mask[row] = m;
            h[row]    = z * m;
        } else {
            h[row] = z;
        }
    }
}

// ---------------- transpose: in[R,C] -> out[C,R] ----------------
__global__ void transpose_kernel(const float* __restrict__ in, float* __restrict__ out,
                                 int R, int C)
{
    __shared__ float tile[32][33];
    int x = blockIdx.x * 32 + threadIdx.x;
    int y = blockIdx.y * 32 + threadIdx.y;
    #pragma unroll
    for (int j = 0; j < 32; j += 8)
        tile[threadIdx.y + j][threadIdx.x] = in[(size_t)(y + j) * C + x];
    __syncthreads();
    int ox = blockIdx.y * 32 + threadIdx.x;
    int oy = blockIdx.x * 32 + threadIdx.y;
    #pragma unroll
    for (int j = 0; j < 32; j += 8)
        out[(size_t)(oy + j) * R + ox] = tile[threadIdx.x][threadIdx.y + j];
}

// ---------------- diag fill: out[N,N] = diag(d) (d==nullptr -> identity) ----------------
__global__ void diagfill_kernel(float* __restrict__ out, const float* __restrict__ d, int N)
{
    size_t idx = ((size_t)blockIdx.x * blockDim.x + threadIdx.x) * 4;
    size_t total = (size_t)N * N;
    if (idx >= total) return;
    size_t row = idx / N;
    size_t col = idx - row * N;
    float4 v = make_float4(0.f, 0.f, 0.f, 0.f);
    if (row >= col && row < col + 4) {
        float dv = d ? d[row] : 1.0f;
        ((float*)&v)[row - col] = dv;
    }
    *(float4*)(out + idx) = v;
}

// ---------------- build sorted index list of nonzero mask entries ----------------
__global__ void build_idx_kernel(const float* __restrict__ mask, int n,
                                 int* __restrict__ idx, int* __restrict__ cnt)
{
    __shared__ int sdata[1024];
    __shared__ int sbase;
    int tid = threadIdx.x;
    if (tid == 0) sbase = 0;
    __syncthreads();
    for (int chunk = 0; chunk < n; chunk += 1024) {
        int i = chunk + tid;
        int flag = (i < n && mask[i] != 0.f) ? 1 : 0;
        sdata[tid] = flag;
        __syncthreads();
        #pragma unroll
        for (int off = 1; off < 1024; off <<= 1) {
            int v = (tid >= off) ? sdata[tid - off] : 0;
            __syncthreads();
            sdata[tid] += v;
            __syncthreads();
        }
        int incl  = sdata[tid];
        int total = sdata[1023];
        if (flag) idx[sbase + incl - 1] = i;
        __syncthreads();
        if (tid == 0) sbase += total;
        __syncthreads();
    }
    if (tid == 0) {
        cnt[0] = sbase;
        cnt[1] = (sbase + 31) & ~31;
    }
}

// ---------------- gather kernels (pad zeros; outputs pre-rounded to tf32) ----------------
__global__ void gatherRC_kernel(const float* __restrict__ src, int sld,
                                const int* __restrict__ ridx, const int* __restrict__ cidx,
                                const int* __restrict__ cntr, const int* __restrict__ cntc,
                                float* __restrict__ out)
{
    int r = blockIdx.x;
    int rc = cntr[0], rp = cntr[1];
    int cc = cntc[0], cp = cntc[1];
    if (r >= rp) return;
    bool ok = (r < rc);
    const float* s = src + (size_t)(ok ? ridx[r] : 0) * sld;
    float* o = out + (size_t)r * cp;
    for (int j = threadIdx.x; j < cp; j += blockDim.x)
        o[j] = (ok && j < cc) ? f2tf32f(s[cidx[j]]) : 0.f;
}

__global__ void gatherC_kernel(const float* __restrict__ src, int sld,
                               const int* __restrict__ cidx, const int* __restrict__ cntc,
                               float* __restrict__ out)
{
    int r = blockIdx.x;
    int cc = cntc[0], cp = cntc[1];
    const float* s = src + (size_t)r * sld;
    float* o = out + (size_t)r * cp;
    for (int j = threadIdx.x; j < cp; j += blockDim.x)
        o[j] = (j < cc) ? f2tf32f(s[cidx[j]]) : 0.f;
}

__global__ void gatherR_kernel(const float* __restrict__ src, int sld,
                               const int* __restrict__ ridx, const int* __restrict__ cntr,
                               float* __restrict__ out, int ncols)
{
    int r = blockIdx.x;
    int rc = cntr[0], rp = cntr[1];
    if (r >= rp) return;
    bool ok = (r < rc);
    const float* s = src + (size_t)(ok ? ridx[r] : 0) * sld;
    float* o = out + (size_t)r * ncols;
    for (int j = threadIdx.x * 4; j < ncols; j += blockDim.x * 4) {
        float4 v = ok ? *(const float4*)(s + j) : make_float4(0.f, 0.f, 0.f, 0.f);
        v.x = f2tf32f(v.x); v.y = f2tf32f(v.y); v.z = f2tf32f(v.z); v.w = f2tf32f(v.w);
        *(float4*)(o + j) = v;
    }
}

// ---------------- tf32 tensor-core GEMM, cp.async double-buffered ----------------
// C[M,N] = A[M,K] @ B[K,N]; inputs pre-rounded tf32 bits. K = kp[1] (mult of 32),
// blocks with row-base >= mp[1] exit. N fixed = 2048.
#define BM  128
#define BN  128
#define BKT 32
#define NDIM 2048
#define ASTR 36
#define BSTR 136
#define SMEM_A_WORDS (BM * ASTR)      // 4608
#define SMEM_B_WORDS (BKT * BSTR)     // 4352
#define GEMM_SMEM_BYTES ((2 * SMEM_A_WORDS + 2 * SMEM_B_WORDS) * 4)  // 71680

__device__ __forceinline__ void cp16(float* smem_dst, const float* gmem_src) {
    unsigned s = (unsigned)__cvta_generic_to_shared(smem_dst);
    asm volatile("cp.async.ca.shared.global [%0], [%1], 16;\n" :: "r"(s), "l"(gmem_src));
}

template<bool OUT_TF32>
__global__ __launch_bounds__(256)
void tf32gemm_kernel(const int* __restrict__ kp, const int* __restrict__ mp,
                     const float* __restrict__ A, const float* __restrict__ B,
                     float* __restrict__ C)
{
    if ((int)(blockIdx.y * BM) >= mp[1]) return;
    const int K = kp[1];

    extern __shared__ float sm[];
    float* As = sm;                          // [2][BM*ASTR]
    float* Bs = sm + 2 * SMEM_A_WORDS;       // [2][BKT*BSTR]

    const int tid  = threadIdx.x;
    const int wid  = tid / 32;
    const int lane = tid % 32;
    const int g    = lane >> 2;
    const int t    = lane & 3;
    const int warpM = wid % 4;
    const int warpN = wid / 4;

    const size_t aBase = (size_t)blockIdx.y * BM * K;
    const size_t cBase = (size_t)blockIdx.y * BM * NDIM + blockIdx.x * BN;
    const int    bCol  = blockIdx.x * BN;

    // cp.async mapping: A tile 128x32 floats (8 chunks/row, 2 thr/row, 4 chunks/thr)
    const int arow = tid >> 1;
    const int acol = (tid & 1) * 16;         // float offset of first chunk
    // B tile 32x128 floats (32 chunks/row, 8 thr/row, 4 chunks/thr)
    const int brow = tid >> 3;
    const int bcol = (tid & 7) * 16;

    float acc[2][8][4];
    #pragma unroll
    for (int i = 0; i < 2; i++)
        #pragma unroll
        for (int j = 0; j < 8; j++)
            #pragma unroll
            for (int q = 0; q < 4; q++) acc[i][j][q] = 0.f;

    const int nIter = K / BKT;

    // prologue: stage 0
    {
        const float* ag = &A[aBase + (size_t)arow * K + acol];
        float* as = &As[arow * ASTR + acol];
        #pragma unroll
        for (int c = 0; c < 4; c++) cp16(as + c * 4, ag + c * 4);
        const float* bg = &B[(size_t)brow * NDIM + bCol + bcol];
        float* bs = &Bs[brow * BSTR + bcol];
        #pragma unroll
        for (int c = 0; c < 4; c++) cp16(bs + c * 4, bg + c * 4);
        asm volatile("cp.async.commit_group;\n");
    }

    for (int it = 0; it < nIter; it++) {
        const int cur = it & 1;
        if (it + 1 < nIter) {
            const int nxt = cur ^ 1;
            const int bk = (it + 1) * BKT;
            const float* ag = &A[aBase + (size_t)arow * K + bk + acol];
            float* as = &As[nxt * SMEM_A_WORDS + arow * ASTR + acol];
            #pragma unroll
            for (int c = 0; c < 4; c++) cp16(as + c * 4, ag + c * 4);
            const float* bg = &B[(size_t)(bk + brow) * NDIM + bCol + bcol];
            float* bs = &Bs[nxt * SMEM_B_WORDS + brow * BSTR + bcol];
            #pragma unroll
            for (int c = 0; c < 4; c++) cp16(bs + c * 4, bg + c * 4);
            asm volatile("cp.async.commit_group;\n");
            asm volatile("cp.async.wait_group 1;\n");
        } else {
            asm volatile("cp.async.wait_group 0;\n");
        }
        __syncthreads();

        const float* Ac = &As[cur * SMEM_A_WORDS];
        const float* Bc = &Bs[cur * SMEM_B_WORDS];
        #pragma unroll
        for (int kk = 0; kk < BKT; kk += 8) {
            unsigned a[2][4];
            #pragma unroll
            for (int i = 0; i < 2; i++) {
                int mb = warpM * 32 + i * 16;
                a[i][0] = __float_as_uint(Ac[(mb + g)     * ASTR + kk + t]);
                a[i][1] = __float_as_uint(Ac[(mb + g + 8) * ASTR + kk + t]);
                a[i][2] = __float_as_uint(Ac[(mb + g)     * ASTR + kk + t + 4]);
                a[i][3] = __float_as_uint(Ac[(mb + g + 8) * ASTR + kk + t + 4]);
            }
            unsigned b[8][2];
            #pragma unroll
            for (int j = 0; j < 8; j++) {
                int nb = warpN * 64 + j * 8;
                b[j][0] = __float_as_uint(Bc[(kk + t)     * BSTR + nb + g]);
                b[j][1] = __float_as_uint(Bc[(kk + t + 4) * BSTR + nb + g]);
            }
            #pragma unroll
            for (int i = 0; i < 2; i++)
                #pragma unroll
                for (int j = 0; j < 8; j++) {
                    asm volatile(
                        "mma.sync.aligned.m16n8k8.row.col.f32.tf32.tf32.f32 "
                        "{%0,%1,%2,%3}, {%4,%5,%6,%7}, {%8,%9}, {%0,%1,%2,%3};"
                        : "+f"(acc[i][j][0]), "+f"(acc[i][j][1]),
                          "+f"(acc[i][j][2]), "+f"(acc[i][j][3])
                        : "r"(a[i][0]), "r"(a[i][1]), "r"(a[i][2]), "r"(a[i][3]),
                          "r"(b[j][0]), "r"(b[j][1]));
                }
        }
        __syncthreads();
    }

    #pragma unroll
    for (int i = 0; i < 2; i++) {
        int row0 = warpM * 32 + i * 16 + g;
        #pragma unroll
        for (int j = 0; j < 8; j++) {
            int col = warpN * 64 + j * 8 + t * 2;
            float c0 = acc[i][j][0], c1 = acc[i][j][1];
            float c2 = acc[i][j][2], c3 = acc[i][j][3];
            if (OUT_TF32) {
                c0 = f2tf32f(c0); c1 = f2tf32f(c1);
                c2 = f2tf32f(c2); c3 = f2tf32f(c3);
            }
            *(float2*)(&C[cBase + (size_t)row0 * NDIM + col])       = make_float2(c0, c1);
            *(float2*)(&C[cBase + (size_t)(row0 + 8) * NDIM + col]) = make_float2(c2, c3);
        }
    }
}

// ---------------- launch ----------------
extern "C" void kernel_launch(void* const* d_in, const int* in_sizes, int n_in,
                              void* d_out, int out_size)
{
    (void)in_sizes; (void)n_in; (void)out_size;
    const float* x  = (const float*)d_in[0];
    const float* W1 = (const float*)d_in[1];   // [4096, 2048]
    const float* W2 = (const float*)d_in[2];   // [4096, 4096]
    const float* W3 = (const float*)d_in[3];   // [2048, 4096]
    float* out = (float*)d_out;

    float *h1, *m1, *h2, *m2, *Et, *A1, *A2, *B1;
    int *idx1, *idx2, *cnt1, *cnt2, *c2048;
    cudaGetSymbolAddress((void**)&h1, g_h1);
    cudaGetSymbolAddress((void**)&m1, g_m1);
    cudaGetSymbolAddress((void**)&h2, g_h2);
    cudaGetSymbolAddress((void**)&m2, g_m2);
    cudaGetSymbolAddress((void**)&Et, g_Et);
    cudaGetSymbolAddress((void**)&A1, g_A1);
    cudaGetSymbolAddress((void**)&A2, g_A2);
    cudaGetSymbolAddress((void**)&B1, g_B1);
    cudaGetSymbolAddress((void**)&idx1, g_idx1);
    cudaGetSymbolAddress((void**)&idx2, g_idx2);
    cudaGetSymbolAddress((void**)&cnt1, g_cnt1);
    cudaGetSymbolAddress((void**)&cnt2, g_cnt2);
    cudaGetSymbolAddress((void**)&c2048, g_c2048);

    cudaFuncSetAttribute(tf32gemm_kernel<true>,
                         cudaFuncAttributeMaxDynamicSharedMemorySize, GEMM_SMEM_BYTES);
    cudaFuncSetAttribute(tf32gemm_kernel<false>,
                         cudaFuncAttributeMaxDynamicSharedMemorySize, GEMM_SMEM_BYTES);

    // Output offsets (floats)
    const size_t OFF_OUT = 0;
    const size_t OFF_DJM = OFF_OUT + OUTSIZE;
    const size_t OFF_J1  = OFF_DJM + (size_t)INSIZE * OUTSIZE;
    const size_t OFF_J2  = OFF_J1  + (size_t)INSIZE * HSIZE;
    const size_t OFF_J3  = OFF_J2  + (size_t)HSIZE * HSIZE;
    const size_t OFF_J4  = OFF_J3  + (size_t)HSIZE * HSIZE;
    const size_t OFF_J5  = OFF_J4  + (size_t)HSIZE * HSIZE;
    const size_t OFF_J6  = OFF_J5  + (size_t)HSIZE * OUTSIZE;

    // Forward pass (fp32 GEMVs; exact masks matter for correctness)
    gemv_kernel<<<HSIZE,   256>>>(W1, x,  h1, m1, INSIZE);
    gemv_kernel<<<HSIZE,   256>>>(W2, h1, h2, m2, HSIZE);
    gemv_kernel<<<OUTSIZE, 256>>>(W3, h2, out + OFF_OUT, nullptr, HSIZE);

    // Jacobian transposes into output slots (reused as gather sources)
    {
        dim3 blk(32, 8);
        transpose_kernel<<<dim3(INSIZE/32, HSIZE/32), blk>>>(W1, out + OFF_J1, HSIZE, INSIZE);
        transpose_kernel<<<dim3(HSIZE/32,  HSIZE/32), blk>>>(W2, out + OFF_J3, HSIZE, HSIZE);
        transpose_kernel<<<dim3(HSIZE/32,  OUTSIZE/32), blk>>>(W3, out + OFF_J5, OUTSIZE, HSIZE);
    }
    {
        size_t nH = ((size_t)HSIZE * HSIZE) / 4;
        size_t nO = ((size_t)OUTSIZE * OUTSIZE) / 4;
        diagfill_kernel<<<(unsigned)((nH + 255) / 256), 256>>>(out + OFF_J2, m1, HSIZE);
        diagfill_kernel<<<(unsigned)((nH + 255) / 256), 256>>>(out + OFF_J4, m2, HSIZE);
        diagfill_kernel<<<(unsigned)((nO + 255) / 256), 256>>>(out + OFF_J6, nullptr, OUTSIZE);
    }

    // Sparsity compaction (pre-rounded tf32 outputs)
    build_idx_kernel<<<1, 1024>>>(m1, HSIZE, idx1, cnt1);
    build_idx_kernel<<<1, 1024>>>(m2, HSIZE, idx2, cnt2);
    gatherRC_kernel<<<HSIZE, 256>>>(out + OFF_J3, HSIZE, idx1, idx2, cnt1, cnt2, A1);
    gatherR_kernel<<<HSIZE, 256>>>(out + OFF_J5, OUTSIZE, idx2, cnt2, B1, OUTSIZE);
    gatherC_kernel<<<INSIZE, 256>>>(out + OFF_J1, HSIZE, idx1, cnt1, A2);

    // GEMM1: Et[n1p, 2048] = A1 @ B1 (tf32-rounded output feeds GEMM2)
    tf32gemm_kernel<true><<<dim3(NDIM / BN, HSIZE / BM), 256, GEMM_SMEM_BYTES>>>(
        cnt2, cnt1, A1, B1, Et);
    // GEMM2: DJM[2048, 2048] = A2 @ Et
    tf32gemm_kernel<false><<<dim3(NDIM / BN, INSIZE / BM), 256, GEMM_SMEM_BYTES>>>(
        cnt1, c2048, A2, Et, out + OFF_DJM);
}